// round 5
// baseline (speedup 1.0000x reference)
#include <cuda_runtime.h>
#include <cuda_bf16.h>
#include <math.h>
#include <stdint.h>

// ---------------- problem constants ----------------
#define HHs   56
#define NTOK  100352
#define WN    49
#define NC_A  6      // K=384  -> 6 chunks of 64
#define NC_H  24     // K=1536 -> 24 chunks of 64

// ---------------- scratch: chunk-major, pre-swizzled layouts ----------------
__device__ __align__(1024) __nv_bfloat16 g_act[(size_t)12 * NTOK * 64];
__device__ __align__(1024) __nv_bfloat16 g_hid[(size_t)48 * NTOK * 64];
__device__ __align__(256) float g_qkv [(size_t)NTOK * 1152];
__device__ __align__(256) float g_xres[(size_t)NTOK * 384];
__device__ __align__(1024) __nv_bfloat16 g_wq[(size_t)12 * 1152 * 64];
__device__ __align__(1024) __nv_bfloat16 g_wp[(size_t)12 *  384 * 64];
__device__ __align__(1024) __nv_bfloat16 g_w1[(size_t)12 * 1536 * 64];
__device__ __align__(1024) __nv_bfloat16 g_w2[(size_t)48 *  384 * 64];

// ---------------- PTX helpers ----------------
__device__ __forceinline__ uint32_t smem_u32(const void* p) {
    uint32_t a;
    asm("{ .reg .u64 t; cvta.to.shared.u64 t, %1; cvt.u32.u64 %0, t; }" : "=r"(a) : "l"(p));
    return a;
}
#define MBARRIER_INIT(mb, c) \
    asm volatile("mbarrier.init.shared.b64 [%0], %1;" :: "r"((uint32_t)(mb)), "r"((uint32_t)(c)) : "memory")
#define MBARRIER_EXPECT_TX(mb, n) \
    asm volatile("mbarrier.arrive.expect_tx.shared.b64 _, [%0], %1;" :: "r"((uint32_t)(mb)), "r"((uint32_t)(n)) : "memory")
#define MBARRIER_WAIT_PARITY(mb, par) do { \
    uint32_t _m = (uint32_t)(mb), _p = (uint32_t)(par), _d; \
    asm volatile("{\n\t.reg .pred p;\n\t" \
        "mbarrier.try_wait.parity.acquire.cta.shared::cta.b64 p, [%1], %2;\n\t" \
        "selp.b32 %0, 1, 0, p;\n\t}" : "=r"(_d) : "r"(_m), "r"(_p) : "memory"); \
    if (!_d) { \
        asm volatile("{\n\t.reg .pred P1;\n\t" \
            "WL_%=:\n\t" \
            "mbarrier.try_wait.parity.acquire.cta.shared::cta.b64 P1, [%0], %1, 0x989680;\n\t" \
            "@P1 bra.uni WD_%=;\n\t" \
            "bra.uni WL_%=;\n\t" \
            "WD_%=:\n\t}" :: "r"(_m), "r"(_p) : "memory"); \
    } } while (0)
#define BULK_G2S(dst, src, n, mb) \
    asm volatile("cp.async.bulk.shared::cluster.global.mbarrier::complete_tx::bytes [%0], [%1], %2, [%3];" \
        :: "r"((uint32_t)(dst)), "l"(src), "r"((uint32_t)(n)), "r"((uint32_t)(mb)) : "memory")
#define FENCE_ASYNC() asm volatile("fence.proxy.async.shared::cta;" ::: "memory")
#define LDSM_X4(r0, r1, r2, r3, addr) \
    asm volatile("ldmatrix.sync.aligned.m8n8.x4.shared.b16 {%0,%1,%2,%3}, [%4];" \
                 : "=r"(r0), "=r"(r1), "=r"(r2), "=r"(r3) : "r"(addr))

__device__ __forceinline__ void mma16816(float* c, const uint32_t* a, const uint32_t* b) {
    asm volatile("mma.sync.aligned.m16n8k16.row.col.f32.bf16.bf16.f32 "
        "{%0,%1,%2,%3}, {%4,%5,%6,%7}, {%8,%9}, {%0,%1,%2,%3};"
        : "+f"(c[0]), "+f"(c[1]), "+f"(c[2]), "+f"(c[3])
        : "r"(a[0]), "r"(a[1]), "r"(a[2]), "r"(a[3]), "r"(b[0]), "r"(b[1]));
}

// window-order row -> sequence row (roll map; same both directions)
__device__ __forceinline__ int win_to_seq(int r) {
    int n  = r % WN;
    int t  = r / WN;
    int wc = t & 7, wr = (t >> 3) & 7, b = t >> 6;
    int n7 = n / 7;
    int h = wr * 7 + n7, w = wc * 7 + (n - n7 * 7);
    int dh = h + 3; if (dh >= HHs) dh -= HHs;
    int dw = w + 3; if (dw >= HHs) dw -= HHs;
    return (b * HHs + dh) * HHs + dw;
}

// split hi/lo store of 2 adjacent cols into chunk-major swizzled layout
__device__ __forceinline__ void split_store2(__nv_bfloat16* base, int nc, int rows,
                                             int tok, int k, float v0, float v1) {
    int ch  = k >> 6;
    int idx = ((((k >> 3) & 7) ^ (tok & 7)) << 3) + (k & 7);
    __nv_bfloat16 h0 = __float2bfloat16(v0), h1 = __float2bfloat16(v1);
    __nv_bfloat162 hp; hp.x = h0; hp.y = h1;
    __nv_bfloat162 lp;
    lp.x = __float2bfloat16(v0 - __bfloat162float(h0));
    lp.y = __float2bfloat16(v1 - __bfloat162float(h1));
    *(__nv_bfloat162*)(base + ((size_t)ch        * rows + tok) * 64 + idx) = hp;
    *(__nv_bfloat162*)(base + ((size_t)(nc + ch) * rows + tok) * 64 + idx) = lp;
}

// ---------------- weight prep: W[K][N] fp32 -> [2*NC][N][64] swizzled ----------------
__global__ void wprep(const float* __restrict__ W, int K, int N, __nv_bfloat16* __restrict__ O)
{
    __shared__ float t[32][33];
    int nb = blockIdx.x * 32, kb = blockIdx.y * 32;
    for (int i = threadIdx.y; i < 32; i += 8)
        t[i][threadIdx.x] = W[(size_t)(kb + i) * N + nb + threadIdx.x];
    __syncthreads();
    int NC = K >> 6;
    for (int i = threadIdx.y; i < 32; i += 8) {
        float v = t[threadIdx.x][i];
        int k = kb + threadIdx.x, n = nb + i;
        __nv_bfloat16 h = __float2bfloat16(v);
        __nv_bfloat16 l = __float2bfloat16(v - __bfloat162float(h));
        int ch  = k >> 6;
        int idx = ((((k >> 3) & 7) ^ (n & 7)) << 3) + (k & 7);
        O[((size_t)ch        * N + n) * 64 + idx] = h;
        O[((size_t)(NC + ch) * N + n) * 64 + idx] = l;
    }
}

// ---------------- LayerNorm -> split chunked bf16 (one warp per token) ----------------
template<bool PERM>
__global__ void ln_kernel(const float* __restrict__ X, const float* __restrict__ G,
                          const float* __restrict__ Bv, __nv_bfloat16* __restrict__ Y)
{
    int gw   = (blockIdx.x * blockDim.x + threadIdx.x) >> 5;
    int lane = threadIdx.x & 31;
    if (gw >= NTOK) return;
    int src = PERM ? win_to_seq(gw) : gw;
    const float4* xr = (const float4*)(X + (size_t)src * 384);
    float4 a = xr[lane], b = xr[32 + lane], c = xr[64 + lane];
    float s = a.x+a.y+a.z+a.w + b.x+b.y+b.z+b.w + c.x+c.y+c.z+c.w;
    float q = a.x*a.x+a.y*a.y+a.z*a.z+a.w*a.w
            + b.x*b.x+b.y*b.y+b.z*b.z+b.w*b.w
            + c.x*c.x+c.y*c.y+c.z*c.z+c.w*c.w;
    #pragma unroll
    for (int o = 16; o; o >>= 1) {
        s += __shfl_xor_sync(0xffffffffu, s, o);
        q += __shfl_xor_sync(0xffffffffu, q, o);
    }
    float mu  = s * (1.0f / 384.0f);
    float var = q * (1.0f / 384.0f) - mu * mu;
    float rs  = rsqrtf(var + 1e-5f);
    const float4* gg = (const float4*)G;
    const float4* bb = (const float4*)Bv;
    #pragma unroll
    for (int seg = 0; seg < 3; seg++) {
        float4 v  = (seg == 0) ? a : (seg == 1) ? b : c;
        float4 g4 = gg[seg * 32 + lane];
        float4 b4 = bb[seg * 32 + lane];
        int k0 = seg * 128 + lane * 4;
        float w0 = (v.x - mu) * rs * g4.x + b4.x;
        float w1 = (v.y - mu) * rs * g4.y + b4.y;
        float w2 = (v.z - mu) * rs * g4.z + b4.z;
        float w3 = (v.w - mu) * rs * g4.w + b4.w;
        split_store2(Y, NC_A, NTOK, gw, k0,     w0, w1);
        split_store2(Y, NC_A, NTOK, gw, k0 + 2, w2, w3);
    }
}

// ---------------- attention: 1 thread per row, broadcast smem k/v ----------------
__global__ __launch_bounds__(64)
void attn_kernel(const float* __restrict__ qkv, __nv_bfloat16* __restrict__ O)
{
    __shared__ float4 kk[WN * 8], vv[WN * 8];
    int win = blockIdx.x, head = blockIdx.y;
    int t = threadIdx.x;
    const float* base = qkv + (size_t)win * WN * 1152 + head * 32;
    for (int u = t; u < WN * 8; u += 64) {
        int m = u >> 3, j = u & 7;
        kk[u] = *(const float4*)(base + (size_t)m * 1152 + 384 + j * 4);
        vv[u] = *(const float4*)(base + (size_t)m * 1152 + 768 + j * 4);
    }
    __syncthreads();
    if (t >= WN) return;
    float q[32];
    const float4* qr = (const float4*)(base + (size_t)t * 1152);
    #pragma unroll
    for (int j = 0; j < 8; j++) {
        float4 f = qr[j];
        q[4*j] = f.x; q[4*j+1] = f.y; q[4*j+2] = f.z; q[4*j+3] = f.w;
    }
    float s[WN];
    #pragma unroll
    for (int m = 0; m < WN; m++) {
        float a = 0.0f;
        #pragma unroll
        for (int j = 0; j < 8; j++) {
            float4 f = kk[m*8 + j];
            a += q[4*j]*f.x + q[4*j+1]*f.y + q[4*j+2]*f.z + q[4*j+3]*f.w;
        }
        s[m] = a * 0.17677669529663687f;
    }
    float mx = -1e30f;
    #pragma unroll
    for (int m = 0; m < WN; m++) mx = fmaxf(mx, s[m]);
    float sum = 0.0f;
    #pragma unroll
    for (int m = 0; m < WN; m++) { s[m] = __expf(s[m] - mx); sum += s[m]; }
    float inv = 1.0f / sum;
    float o[32];
    #pragma unroll
    for (int j = 0; j < 32; j++) o[j] = 0.0f;
    #pragma unroll
    for (int m = 0; m < WN; m++) {
        float w = s[m] * inv;
        #pragma unroll
        for (int j = 0; j < 8; j++) {
            float4 f = vv[m*8 + j];
            o[4*j] += w*f.x; o[4*j+1] += w*f.y; o[4*j+2] += w*f.z; o[4*j+3] += w*f.w;
        }
    }
    int tok = win * WN + t;
    int k0 = head * 32;
    #pragma unroll
    for (int j = 0; j < 32; j += 2)
        split_store2(O, NC_A, NTOK, tok, k0 + j, o[j], o[j + 1]);
}

// ---------------- bf16x3 mma.sync GEMM, 256x128 CTA, 4-stage bulk pipeline ----------------
#define STAGES 4
#define STG_BYTES 49152              // A 32KB + B 16KB
#define MBAR_OFF  196608
#define SMEM_DYN  (196608 + 64)

// EPI 0: qkv fp32   1: gelu -> chunked hid   2: scatter+resid fp32   3: resid fp32
template<int EPI>
__global__ __launch_bounds__(256)
void gemm_mma(const __nv_bfloat16* __restrict__ A, const __nv_bfloat16* __restrict__ B,
              const float* __restrict__ bias, float* __restrict__ Co,
              __nv_bfloat16* __restrict__ O2, const float* __restrict__ resid,
              int NC, int Nn)
{
    extern __shared__ __align__(1024) char sm[];
    uint32_t sb = smem_u32(sm);
    int tid = threadIdx.x, lane = tid & 31, wid = tid >> 5;
    int wm = wid & 3, wn = wid >> 2;           // 4(M) x 2(N) warps, warp tile 64x64
    int m0 = blockIdx.y * 256, n0 = blockIdx.x * 128;
    int NK = NC * 3;

    if (tid == 0) {
        #pragma unroll
        for (int s = 0; s < STAGES; s++) MBARRIER_INIT(sb + MBAR_OFF + s * 8, 1);
        FENCE_ASYNC();
    }
    __syncthreads();

    auto issue = [&](int idx) {
        int j = idx / 3, t3 = idx - 3 * j;
        int ach = j + (t3 == 1 ? NC : 0);
        int bch = j + (t3 == 2 ? NC : 0);
        const char* asrc = (const char*)A + ((size_t)ach * NTOK + m0) * 128;
        const char* bsrc = (const char*)B + ((size_t)bch * Nn   + n0) * 128;
        int s = idx % STAGES;
        uint32_t dst = sb + s * STG_BYTES;
        uint32_t mb  = sb + MBAR_OFF + s * 8;
        MBARRIER_EXPECT_TX(mb, 49152);
        BULK_G2S(dst,         asrc, 32768, mb);
        BULK_G2S(dst + 32768, bsrc, 16384, mb);
    };
    if (tid == 0) { issue(0); issue(1); issue(2); issue(3); }

    float acc[4][8][4];
    #pragma unroll
    for (int i = 0; i < 4; i++)
        #pragma unroll
        for (int j = 0; j < 8; j++)
            #pragma unroll
            for (int u = 0; u < 4; u++) acc[i][j][u] = 0.0f;

    for (int i = 0; i < NK; i++) {
        int s = i % STAGES;
        MBARRIER_WAIT_PARITY(sb + MBAR_OFF + s * 8, (i / STAGES) & 1);

        uint32_t As = sb + s * STG_BYTES;
        uint32_t Bs = As + 32768;
        #pragma unroll
        for (int kk = 0; kk < 4; kk++) {
            int ch = kk * 2 + (lane >> 4);
            uint32_t b[8][2];
            #pragma unroll
            for (int j2 = 0; j2 < 4; j2++) {
                int row = wn * 64 + j2 * 16 + (lane & 15);
                uint32_t addr = Bs + (uint32_t)row * 128 + (uint32_t)((ch ^ (row & 7)) << 4);
                uint32_t r0, r1, r2, r3;
                LDSM_X4(r0, r1, r2, r3, addr);
                b[2*j2][0] = r0; b[2*j2][1] = r2;
                b[2*j2+1][0] = r1; b[2*j2+1][1] = r3;
            }
            #pragma unroll
            for (int ii = 0; ii < 4; ii++) {
                int row = wm * 64 + ii * 16 + (lane & 15);
                uint32_t addr = As + (uint32_t)row * 128 + (uint32_t)((ch ^ (row & 7)) << 4);
                uint32_t a[4];
                LDSM_X4(a[0], a[1], a[2], a[3], addr);
                #pragma unroll
                for (int j = 0; j < 8; j++) mma16816(acc[ii][j], a, b[j]);
            }
        }
        __syncthreads();
        if (tid == 0 && i + STAGES < NK) issue(i + STAGES);
    }

    // epilogue: 2 passes of 128 rows through smem (stride 132)
    float* smf = (float*)sm;
    for (int pass = 0; pass < 2; pass++) {
        __syncthreads();
        if ((wm >> 1) == pass) {
            int rbase = (wm & 1) * 64;
            #pragma unroll
            for (int i = 0; i < 4; i++)
                #pragma unroll
                for (int j = 0; j < 8; j++) {
                    int br = rbase + i * 16 + (lane >> 2);
                    int bc = wn * 64 + j * 8 + 2 * (lane & 3);
                    *(float2*)&smf[br * 132 + bc]       = make_float2(acc[i][j][0], acc[i][j][1]);
                    *(float2*)&smf[(br + 8) * 132 + bc] = make_float2(acc[i][j][2], acc[i][j][3]);
                }
        }
        __syncthreads();

        int r    = tid >> 1;
        int cb0  = (tid & 1) * 64;
        int grow = m0 + pass * 128 + r;
        const float* srow = &smf[r * 132 + cb0];
        if (EPI == 0) {
            float* dst = Co + (size_t)grow * Nn + n0 + cb0;
            #pragma unroll
            for (int c = 0; c < 64; c += 4) {
                float4 o;
                o.x = srow[c+0] + bias[n0+cb0+c+0];
                o.y = srow[c+1] + bias[n0+cb0+c+1];
                o.z = srow[c+2] + bias[n0+cb0+c+2];
                o.w = srow[c+3] + bias[n0+cb0+c+3];
                *(float4*)(dst + c) = o;
            }
        } else if (EPI == 1) {
            int gc0   = n0 + cb0;
            int ch    = gc0 >> 6;
            int ncout = Nn >> 6;
            __nv_bfloat16* hi = O2 + ((size_t)ch           * NTOK + grow) * 64;
            __nv_bfloat16* lo = O2 + ((size_t)(ncout + ch) * NTOK + grow) * 64;
            #pragma unroll
            for (int c = 0; c < 64; c += 2) {
                float v0 = srow[c]   + bias[gc0 + c];
                float v1 = srow[c+1] + bias[gc0 + c + 1];
                v0 = 0.5f * v0 * (1.0f + erff(v0 * 0.70710678118654752f));
                v1 = 0.5f * v1 * (1.0f + erff(v1 * 0.70710678118654752f));
                int idx = ((((c >> 3) & 7) ^ (grow & 7)) << 3) + (c & 7);
                __nv_bfloat16 h0 = __float2bfloat16(v0), h1 = __float2bfloat16(v1);
                __nv_bfloat162 hp; hp.x = h0; hp.y = h1;
                __nv_bfloat162 lp;
                lp.x = __float2bfloat16(v0 - __bfloat162float(h0));
                lp.y = __float2bfloat16(v1 - __bfloat162float(h1));
                *(__nv_bfloat162*)(hi + idx) = hp;
                *(__nv_bfloat162*)(lo + idx) = lp;
            }
        } else {
            size_t orow = (EPI == 2) ? (size_t)win_to_seq(grow) * Nn : (size_t)grow * Nn;
            float* dst = Co + orow + n0 + cb0;
            const float* rp = resid + orow + n0 + cb0;
            #pragma unroll
            for (int c = 0; c < 64; c += 4) {
                float4 rr = *(const float4*)(rp + c);
                float4 o;
                o.x = srow[c+0] + bias[n0+cb0+c+0] + rr.x;
                o.y = srow[c+1] + bias[n0+cb0+c+1] + rr.y;
                o.z = srow[c+2] + bias[n0+cb0+c+2] + rr.z;
                o.w = srow[c+3] + bias[n0+cb0+c+3] + rr.w;
                *(float4*)(dst + c) = o;
            }
        }
    }
}

// ---------------- launcher ----------------
extern "C" void kernel_launch(void* const* d_in, const int* in_sizes, int n_in,
                              void* d_out, int out_size)
{
    const float* x      = (const float*)d_in[0];
    const float* ln1_g  = (const float*)d_in[1];
    const float* ln1_b  = (const float*)d_in[2];
    const float* w_qkv  = (const float*)d_in[3];
    const float* b_qkv  = (const float*)d_in[4];
    const float* w_proj = (const float*)d_in[5];
    const float* b_proj = (const float*)d_in[6];
    const float* ln2_g  = (const float*)d_in[7];
    const float* ln2_b  = (const float*)d_in[8];
    const float* w_fc1  = (const float*)d_in[9];
    const float* b_fc1  = (const float*)d_in[10];
    const float* w_fc2  = (const float*)d_in[11];
    const float* b_fc2  = (const float*)d_in[12];
    float* out = (float*)d_out;

    __nv_bfloat16 *act, *hid, *wq, *wp, *w1, *w2;
    float *qkv, *xres;
    cudaGetSymbolAddress((void**)&act,  g_act);
    cudaGetSymbolAddress((void**)&hid,  g_hid);
    cudaGetSymbolAddress((void**)&qkv,  g_qkv);
    cudaGetSymbolAddress((void**)&xres, g_xres);
    cudaGetSymbolAddress((void**)&wq,   g_wq);
    cudaGetSymbolAddress((void**)&wp,   g_wp);
    cudaGetSymbolAddress((void**)&w1,   g_w1);
    cudaGetSymbolAddress((void**)&w2,   g_w2);

    cudaFuncSetAttribute(gemm_mma<0>, cudaFuncAttributeMaxDynamicSharedMemorySize, SMEM_DYN);
    cudaFuncSetAttribute(gemm_mma<1>, cudaFuncAttributeMaxDynamicSharedMemorySize, SMEM_DYN);
    cudaFuncSetAttribute(gemm_mma<2>, cudaFuncAttributeMaxDynamicSharedMemorySize, SMEM_DYN);
    cudaFuncSetAttribute(gemm_mma<3>, cudaFuncAttributeMaxDynamicSharedMemorySize, SMEM_DYN);

    // weight prep
    wprep<<<dim3(1152/32,  384/32), dim3(32, 8)>>>(w_qkv,  384,  1152, wq);
    wprep<<<dim3( 384/32,  384/32), dim3(32, 8)>>>(w_proj, 384,   384, wp);
    wprep<<<dim3(1536/32,  384/32), dim3(32, 8)>>>(w_fc1,  384,  1536, w1);
    wprep<<<dim3( 384/32, 1536/32), dim3(32, 8)>>>(w_fc2,  1536,  384, w2);

    const int MT = NTOK / 256;   // 392

    // 1) LN1 + roll + window partition -> act
    ln_kernel<true><<<NTOK / 8, 256>>>(x, ln1_g, ln1_b, act);
    // 2) QKV
    gemm_mma<0><<<dim3(1152/128, MT), 256, SMEM_DYN>>>(act, wq, b_qkv, qkv, nullptr, nullptr, NC_A, 1152);
    // 3) attention -> act
    attn_kernel<<<dim3(NTOK / WN, 12), 64>>>(qkv, act);
    // 4) proj + reverse/roll + residual
    gemm_mma<2><<<dim3( 384/128, MT), 256, SMEM_DYN>>>(act, wp, b_proj, xres, nullptr, x, NC_A, 384);
    // 5) LN2 -> act
    ln_kernel<false><<<NTOK / 8, 256>>>(xres, ln2_g, ln2_b, act);
    // 6) FC1 + GELU -> hid
    gemm_mma<1><<<dim3(1536/128, MT), 256, SMEM_DYN>>>(act, w1, b_fc1, nullptr, hid, nullptr, NC_A, 1536);
    // 7) FC2 + residual -> out
    gemm_mma<3><<<dim3( 384/128, MT), 256, SMEM_DYN>>>(hid, w2, b_fc2, out, nullptr, xres, NC_H, 384);
}

// round 6
// speedup vs baseline: 1.6031x; 1.6031x over previous
#include <cuda_runtime.h>
#include <cuda_fp16.h>
#include <math.h>
#include <stdint.h>

// ---------------- problem constants ----------------
#define HHs   56
#define NTOK  100352
#define WN    49
#define NC_A  6      // K=384  -> 6 chunks of 64
#define NC_H  24     // K=1536 -> 24 chunks of 64

// ---------------- scratch: chunk-major, pre-swizzled fp16 layouts ----------------
__device__ __align__(1024) __half g_act[(size_t)NC_A * NTOK * 64];    // single fp16
__device__ __align__(1024) __half g_hid[(size_t)NC_H * NTOK * 64];
__device__ __align__(256) float g_qkv [(size_t)NTOK * 1152];
__device__ __align__(256) float g_xres[(size_t)NTOK * 384];
// weights: [2*NC chunks][N][64] (hi chunks then lo chunks)
__device__ __align__(1024) __half g_wq[(size_t)12 * 1152 * 64];
__device__ __align__(1024) __half g_wp[(size_t)12 *  384 * 64];
__device__ __align__(1024) __half g_w1[(size_t)12 * 1536 * 64];
__device__ __align__(1024) __half g_w2[(size_t)48 *  384 * 64];

// ---------------- PTX helpers ----------------
__device__ __forceinline__ uint32_t smem_u32(const void* p) {
    uint32_t a;
    asm("{ .reg .u64 t; cvta.to.shared.u64 t, %1; cvt.u32.u64 %0, t; }" : "=r"(a) : "l"(p));
    return a;
}
#define MBARRIER_INIT(mb, c) \
    asm volatile("mbarrier.init.shared.b64 [%0], %1;" :: "r"((uint32_t)(mb)), "r"((uint32_t)(c)) : "memory")
#define MBARRIER_EXPECT_TX(mb, n) \
    asm volatile("mbarrier.arrive.expect_tx.shared.b64 _, [%0], %1;" :: "r"((uint32_t)(mb)), "r"((uint32_t)(n)) : "memory")
#define MBARRIER_WAIT_PARITY(mb, par) do { \
    uint32_t _m = (uint32_t)(mb), _p = (uint32_t)(par), _d; \
    asm volatile("{\n\t.reg .pred p;\n\t" \
        "mbarrier.try_wait.parity.acquire.cta.shared::cta.b64 p, [%1], %2;\n\t" \
        "selp.b32 %0, 1, 0, p;\n\t}" : "=r"(_d) : "r"(_m), "r"(_p) : "memory"); \
    if (!_d) { \
        asm volatile("{\n\t.reg .pred P1;\n\t" \
            "WL_%=:\n\t" \
            "mbarrier.try_wait.parity.acquire.cta.shared::cta.b64 P1, [%0], %1, 0x989680;\n\t" \
            "@P1 bra.uni WD_%=;\n\t" \
            "bra.uni WL_%=;\n\t" \
            "WD_%=:\n\t}" :: "r"(_m), "r"(_p) : "memory"); \
    } } while (0)
#define BULK_G2S(dst, src, n, mb) \
    asm volatile("cp.async.bulk.shared::cluster.global.mbarrier::complete_tx::bytes [%0], [%1], %2, [%3];" \
        :: "r"((uint32_t)(dst)), "l"(src), "r"((uint32_t)(n)), "r"((uint32_t)(mb)) : "memory")
#define FENCE_ASYNC() asm volatile("fence.proxy.async.shared::cta;" ::: "memory")
#define LDSM_X4(r0, r1, r2, r3, addr) \
    asm volatile("ldmatrix.sync.aligned.m8n8.x4.shared.b16 {%0,%1,%2,%3}, [%4];" \
                 : "=r"(r0), "=r"(r1), "=r"(r2), "=r"(r3) : "r"(addr))

__device__ __forceinline__ void mma16816(float* c, const uint32_t* a, const uint32_t* b) {
    asm volatile("mma.sync.aligned.m16n8k16.row.col.f32.f16.f16.f32 "
        "{%0,%1,%2,%3}, {%4,%5,%6,%7}, {%8,%9}, {%0,%1,%2,%3};"
        : "+f"(c[0]), "+f"(c[1]), "+f"(c[2]), "+f"(c[3])
        : "r"(a[0]), "r"(a[1]), "r"(a[2]), "r"(a[3]), "r"(b[0]), "r"(b[1]));
}

// window-order row -> sequence row (roll map; same both directions)
__device__ __forceinline__ int win_to_seq(int r) {
    int n  = r % WN;
    int t  = r / WN;
    int wc = t & 7, wr = (t >> 3) & 7, b = t >> 6;
    int n7 = n / 7;
    int h = wr * 7 + n7, w = wc * 7 + (n - n7 * 7);
    int dh = h + 3; if (dh >= HHs) dh -= HHs;
    int dw = w + 3; if (dw >= HHs) dw -= HHs;
    return (b * HHs + dh) * HHs + dw;
}

// fp16 store of 2 adjacent cols into chunk-major swizzled layout (k even)
__device__ __forceinline__ void h_store2(__half* base, int rows, int tok, int k,
                                         float v0, float v1) {
    int ch  = k >> 6;
    int idx = ((((k >> 3) & 7) ^ (tok & 7)) << 3) + (k & 7);
    *(__half2*)(base + ((size_t)ch * rows + tok) * 64 + idx) = __floats2half2_rn(v0, v1);
}

// ---------------- weight prep: W[K][N] fp32 -> [2*NC][N][64] swizzled hi/lo ----------------
__global__ void wprep(const float* __restrict__ W, int K, int N, __half* __restrict__ O)
{
    __shared__ float t[32][33];
    int nb = blockIdx.x * 32, kb = blockIdx.y * 32;
    for (int i = threadIdx.y; i < 32; i += 8)
        t[i][threadIdx.x] = W[(size_t)(kb + i) * N + nb + threadIdx.x];
    __syncthreads();
    int NC = K >> 6;
    for (int i = threadIdx.y; i < 32; i += 8) {
        float v = t[threadIdx.x][i];
        int k = kb + threadIdx.x, n = nb + i;
        __half h = __float2half_rn(v);
        __half l = __float2half_rn(v - __half2float(h));
        int ch  = k >> 6;
        int idx = ((((k >> 3) & 7) ^ (n & 7)) << 3) + (k & 7);
        O[((size_t)ch        * N + n) * 64 + idx] = h;
        O[((size_t)(NC + ch) * N + n) * 64 + idx] = l;
    }
}

// ---------------- LayerNorm -> chunked fp16 (one warp per token) ----------------
template<bool PERM>
__global__ void ln_kernel(const float* __restrict__ X, const float* __restrict__ G,
                          const float* __restrict__ Bv, __half* __restrict__ Y)
{
    int gw   = (blockIdx.x * blockDim.x + threadIdx.x) >> 5;
    int lane = threadIdx.x & 31;
    if (gw >= NTOK) return;
    int src = PERM ? win_to_seq(gw) : gw;
    const float4* xr = (const float4*)(X + (size_t)src * 384);
    float4 a = xr[lane], b = xr[32 + lane], c = xr[64 + lane];
    float s = a.x+a.y+a.z+a.w + b.x+b.y+b.z+b.w + c.x+c.y+c.z+c.w;
    float q = a.x*a.x+a.y*a.y+a.z*a.z+a.w*a.w
            + b.x*b.x+b.y*b.y+b.z*b.z+b.w*b.w
            + c.x*c.x+c.y*c.y+c.z*c.z+c.w*c.w;
    #pragma unroll
    for (int o = 16; o; o >>= 1) {
        s += __shfl_xor_sync(0xffffffffu, s, o);
        q += __shfl_xor_sync(0xffffffffu, q, o);
    }
    float mu  = s * (1.0f / 384.0f);
    float var = q * (1.0f / 384.0f) - mu * mu;
    float rs  = rsqrtf(var + 1e-5f);
    const float4* gg = (const float4*)G;
    const float4* bb = (const float4*)Bv;
    #pragma unroll
    for (int seg = 0; seg < 3; seg++) {
        float4 v  = (seg == 0) ? a : (seg == 1) ? b : c;
        float4 g4 = gg[seg * 32 + lane];
        float4 b4 = bb[seg * 32 + lane];
        int k0 = seg * 128 + lane * 4;
        float w0 = (v.x - mu) * rs * g4.x + b4.x;
        float w1 = (v.y - mu) * rs * g4.y + b4.y;
        float w2 = (v.z - mu) * rs * g4.z + b4.z;
        float w3 = (v.w - mu) * rs * g4.w + b4.w;
        h_store2(Y, NTOK, gw, k0,     w0, w1);
        h_store2(Y, NTOK, gw, k0 + 2, w2, w3);
    }
}

// ---------------- attention: 1 thread per row, broadcast smem k/v ----------------
__global__ __launch_bounds__(64)
void attn_kernel(const float* __restrict__ qkv, __half* __restrict__ O)
{
    __shared__ float4 kk[WN * 8], vv[WN * 8];
    int win = blockIdx.x, head = blockIdx.y;
    int t = threadIdx.x;
    const float* base = qkv + (size_t)win * WN * 1152 + head * 32;
    for (int u = t; u < WN * 8; u += 64) {
        int m = u >> 3, j = u & 7;
        kk[u] = *(const float4*)(base + (size_t)m * 1152 + 384 + j * 4);
        vv[u] = *(const float4*)(base + (size_t)m * 1152 + 768 + j * 4);
    }
    __syncthreads();
    if (t >= WN) return;
    float q[32];
    const float4* qr = (const float4*)(base + (size_t)t * 1152);
    #pragma unroll
    for (int j = 0; j < 8; j++) {
        float4 f = qr[j];
        q[4*j] = f.x; q[4*j+1] = f.y; q[4*j+2] = f.z; q[4*j+3] = f.w;
    }
    float s[WN];
    #pragma unroll
    for (int m = 0; m < WN; m++) {
        float a = 0.0f;
        #pragma unroll
        for (int j = 0; j < 8; j++) {
            float4 f = kk[m*8 + j];
            a += q[4*j]*f.x + q[4*j+1]*f.y + q[4*j+2]*f.z + q[4*j+3]*f.w;
        }
        s[m] = a * 0.17677669529663687f;
    }
    float mx = -1e30f;
    #pragma unroll
    for (int m = 0; m < WN; m++) mx = fmaxf(mx, s[m]);
    float sum = 0.0f;
    #pragma unroll
    for (int m = 0; m < WN; m++) { s[m] = __expf(s[m] - mx); sum += s[m]; }
    float inv = 1.0f / sum;
    float o[32];
    #pragma unroll
    for (int j = 0; j < 32; j++) o[j] = 0.0f;
    #pragma unroll
    for (int m = 0; m < WN; m++) {
        float w = s[m] * inv;
        #pragma unroll
        for (int j = 0; j < 8; j++) {
            float4 f = vv[m*8 + j];
            o[4*j] += w*f.x; o[4*j+1] += w*f.y; o[4*j+2] += w*f.z; o[4*j+3] += w*f.w;
        }
    }
    int tok = win * WN + t;
    int k0 = head * 32;
    #pragma unroll
    for (int j = 0; j < 32; j += 2)
        h_store2(O, NTOK, tok, k0 + j, o[j], o[j + 1]);
}

// ---------------- fp16 2-term GEMM: 128x128 CTA, stage = A + Bh + Bl (48KB), 2 stages ----------------
#define STAGES 2
#define STG_BYTES 49152
#define MBAR_OFF  98304
#define SMEM_DYN  (98304 + 64)

// EPI 0: qkv fp32   1: gelu -> chunked fp16   2: scatter+resid fp32   3: resid fp32
template<int EPI>
__global__ __launch_bounds__(256)
void gemm_mma(const __half* __restrict__ A, const __half* __restrict__ B,
              const float* __restrict__ bias, float* __restrict__ Co,
              __half* __restrict__ O2, const float* __restrict__ resid,
              int NC, int Nn)
{
    extern __shared__ __align__(1024) char sm[];
    uint32_t sb = smem_u32(sm);
    int tid = threadIdx.x, lane = tid & 31, wid = tid >> 5;
    int wm = wid & 1, wn = wid >> 1;           // 2(M) x 4(N) warps, warp tile 64x32
    int m0 = blockIdx.y * 128, n0 = blockIdx.x * 128;

    if (tid == 0) {
        MBARRIER_INIT(sb + MBAR_OFF,     1);
        MBARRIER_INIT(sb + MBAR_OFF + 8, 1);
        FENCE_ASYNC();
    }
    __syncthreads();

    auto issue = [&](int j) {
        const char* asrc  = (const char*)A + ((size_t)j * NTOK + m0) * 128;
        const char* bhsrc = (const char*)B + ((size_t)j        * Nn + n0) * 128;
        const char* blsrc = (const char*)B + ((size_t)(NC + j) * Nn + n0) * 128;
        int s = j & 1;
        uint32_t dst = sb + s * STG_BYTES;
        uint32_t mb  = sb + MBAR_OFF + s * 8;
        MBARRIER_EXPECT_TX(mb, 49152);
        BULK_G2S(dst,         asrc,  16384, mb);
        BULK_G2S(dst + 16384, bhsrc, 16384, mb);
        BULK_G2S(dst + 32768, blsrc, 16384, mb);
    };
    if (tid == 0) { issue(0); issue(1); }

    float acc[4][4][4];
    #pragma unroll
    for (int i = 0; i < 4; i++)
        #pragma unroll
        for (int j = 0; j < 4; j++)
            #pragma unroll
            for (int u = 0; u < 4; u++) acc[i][j][u] = 0.0f;

    for (int i = 0; i < NC; i++) {
        int s = i & 1;
        MBARRIER_WAIT_PARITY(sb + MBAR_OFF + s * 8, (i >> 1) & 1);

        uint32_t As  = sb + s * STG_BYTES;
        uint32_t Bhs = As + 16384;
        uint32_t Bls = As + 32768;
        #pragma unroll
        for (int kk = 0; kk < 4; kk++) {
            int ch = kk * 2 + (lane >> 4);
            // B fragments: hi and lo (each 2 ldsm -> 4 n8 frags)
            uint32_t bh[4][2], bl[4][2];
            #pragma unroll
            for (int j2 = 0; j2 < 2; j2++) {
                int row = wn * 32 + j2 * 16 + (lane & 15);
                uint32_t sw = (uint32_t)((ch ^ (row & 7)) << 4);
                uint32_t r0, r1, r2, r3;
                LDSM_X4(r0, r1, r2, r3, Bhs + (uint32_t)row * 128 + sw);
                bh[2*j2][0] = r0; bh[2*j2][1] = r2;
                bh[2*j2+1][0] = r1; bh[2*j2+1][1] = r3;
                LDSM_X4(r0, r1, r2, r3, Bls + (uint32_t)row * 128 + sw);
                bl[2*j2][0] = r0; bl[2*j2][1] = r2;
                bl[2*j2+1][0] = r1; bl[2*j2+1][1] = r3;
            }
            #pragma unroll
            for (int ii = 0; ii < 4; ii++) {
                int row = wm * 64 + ii * 16 + (lane & 15);
                uint32_t a[4];
                LDSM_X4(a[0], a[1], a[2], a[3],
                        As + (uint32_t)row * 128 + (uint32_t)((ch ^ (row & 7)) << 4));
                #pragma unroll
                for (int j = 0; j < 4; j++) mma16816(acc[ii][j], a, bh[j]);
                #pragma unroll
                for (int j = 0; j < 4; j++) mma16816(acc[ii][j], a, bl[j]);
            }
        }
        __syncthreads();
        if (tid == 0 && i + STAGES < NC) issue(i + STAGES);
    }

    // stage C through smem (fp32, stride 132) for coalesced epilogue
    float* smf = (float*)sm;
    #pragma unroll
    for (int i = 0; i < 4; i++)
        #pragma unroll
        for (int j = 0; j < 4; j++) {
            int br = wm * 64 + i * 16 + (lane >> 2);
            int bc = wn * 32 + j * 8 + 2 * (lane & 3);
            *(float2*)&smf[br * 132 + bc]       = make_float2(acc[i][j][0], acc[i][j][1]);
            *(float2*)&smf[(br + 8) * 132 + bc] = make_float2(acc[i][j][2], acc[i][j][3]);
        }
    __syncthreads();

    int r    = tid >> 1;
    int cb0  = (tid & 1) * 64;
    int grow = m0 + r;
    const float* srow = &smf[r * 132 + cb0];
    if (EPI == 0) {
        float* dst = Co + (size_t)grow * Nn + n0 + cb0;
        #pragma unroll
        for (int c = 0; c < 64; c += 4) {
            float4 o;
            o.x = srow[c+0] + bias[n0+cb0+c+0];
            o.y = srow[c+1] + bias[n0+cb0+c+1];
            o.z = srow[c+2] + bias[n0+cb0+c+2];
            o.w = srow[c+3] + bias[n0+cb0+c+3];
            *(float4*)(dst + c) = o;
        }
    } else if (EPI == 1) {
        int gc0 = n0 + cb0;                    // multiple of 64
        int ch  = gc0 >> 6;
        __half* hp = O2 + ((size_t)ch * NTOK + grow) * 64;
        #pragma unroll
        for (int c = 0; c < 64; c += 2) {
            float v0 = srow[c]   + bias[gc0 + c];
            float v1 = srow[c+1] + bias[gc0 + c + 1];
            v0 = 0.5f * v0 * (1.0f + erff(v0 * 0.70710678118654752f));
            v1 = 0.5f * v1 * (1.0f + erff(v1 * 0.70710678118654752f));
            int idx = ((((c >> 3) & 7) ^ (grow & 7)) << 3) + (c & 7);
            *(__half2*)(hp + idx) = __floats2half2_rn(v0, v1);
        }
    } else {
        size_t orow = (EPI == 2) ? (size_t)win_to_seq(grow) * Nn : (size_t)grow * Nn;
        float* dst = Co + orow + n0 + cb0;
        const float* rp = resid + orow + n0 + cb0;
        #pragma unroll
        for (int c = 0; c < 64; c += 4) {
            float4 rr = *(const float4*)(rp + c);
            float4 o;
            o.x = srow[c+0] + bias[n0+cb0+c+0] + rr.x;
            o.y = srow[c+1] + bias[n0+cb0+c+1] + rr.y;
            o.z = srow[c+2] + bias[n0+cb0+c+2] + rr.z;
            o.w = srow[c+3] + bias[n0+cb0+c+3] + rr.w;
            *(float4*)(dst + c) = o;
        }
    }
}

// ---------------- launcher ----------------
extern "C" void kernel_launch(void* const* d_in, const int* in_sizes, int n_in,
                              void* d_out, int out_size)
{
    const float* x      = (const float*)d_in[0];
    const float* ln1_g  = (const float*)d_in[1];
    const float* ln1_b  = (const float*)d_in[2];
    const float* w_qkv  = (const float*)d_in[3];
    const float* b_qkv  = (const float*)d_in[4];
    const float* w_proj = (const float*)d_in[5];
    const float* b_proj = (const float*)d_in[6];
    const float* ln2_g  = (const float*)d_in[7];
    const float* ln2_b  = (const float*)d_in[8];
    const float* w_fc1  = (const float*)d_in[9];
    const float* b_fc1  = (const float*)d_in[10];
    const float* w_fc2  = (const float*)d_in[11];
    const float* b_fc2  = (const float*)d_in[12];
    float* out = (float*)d_out;

    __half *act, *hid, *wq, *wp, *w1, *w2;
    float *qkv, *xres;
    cudaGetSymbolAddress((void**)&act,  g_act);
    cudaGetSymbolAddress((void**)&hid,  g_hid);
    cudaGetSymbolAddress((void**)&qkv,  g_qkv);
    cudaGetSymbolAddress((void**)&xres, g_xres);
    cudaGetSymbolAddress((void**)&wq,   g_wq);
    cudaGetSymbolAddress((void**)&wp,   g_wp);
    cudaGetSymbolAddress((void**)&w1,   g_w1);
    cudaGetSymbolAddress((void**)&w2,   g_w2);

    cudaFuncSetAttribute(gemm_mma<0>, cudaFuncAttributeMaxDynamicSharedMemorySize, SMEM_DYN);
    cudaFuncSetAttribute(gemm_mma<1>, cudaFuncAttributeMaxDynamicSharedMemorySize, SMEM_DYN);
    cudaFuncSetAttribute(gemm_mma<2>, cudaFuncAttributeMaxDynamicSharedMemorySize, SMEM_DYN);
    cudaFuncSetAttribute(gemm_mma<3>, cudaFuncAttributeMaxDynamicSharedMemorySize, SMEM_DYN);

    // weight prep (hi+lo fp16)
    wprep<<<dim3(1152/32,  384/32), dim3(32, 8)>>>(w_qkv,  384,  1152, wq);
    wprep<<<dim3( 384/32,  384/32), dim3(32, 8)>>>(w_proj, 384,   384, wp);
    wprep<<<dim3(1536/32,  384/32), dim3(32, 8)>>>(w_fc1,  384,  1536, w1);
    wprep<<<dim3( 384/32, 1536/32), dim3(32, 8)>>>(w_fc2,  1536,  384, w2);

    const int MT = NTOK / 128;   // 784

    // 1) LN1 + roll + window partition -> act
    ln_kernel<true><<<NTOK / 8, 256>>>(x, ln1_g, ln1_b, act);
    // 2) QKV
    gemm_mma<0><<<dim3(1152/128, MT), 256, SMEM_DYN>>>(act, wq, b_qkv, qkv, nullptr, nullptr, NC_A, 1152);
    // 3) attention -> act
    attn_kernel<<<dim3(NTOK / WN, 12), 64>>>(qkv, act);
    // 4) proj + reverse/roll + residual
    gemm_mma<2><<<dim3( 384/128, MT), 256, SMEM_DYN>>>(act, wp, b_proj, xres, nullptr, x, NC_A, 384);
    // 5) LN2 -> act
    ln_kernel<false><<<NTOK / 8, 256>>>(xres, ln2_g, ln2_b, act);
    // 6) FC1 + GELU -> hid
    gemm_mma<1><<<dim3(1536/128, MT), 256, SMEM_DYN>>>(act, w1, b_fc1, nullptr, hid, nullptr, NC_A, 1536);
    // 7) FC2 + residual -> out
    gemm_mma<3><<<dim3( 384/128, MT), 256, SMEM_DYN>>>(hid, w2, b_fc2, out, nullptr, xres, NC_H, 384);
}

// round 7
// speedup vs baseline: 1.9954x; 1.2447x over previous
#include <cuda_runtime.h>
#include <cuda_fp16.h>
#include <math.h>
#include <stdint.h>

// ---------------- problem constants ----------------
#define HHs   56
#define NTOK  100352
#define WN    49
#define NC_A  6      // K=384  -> 6 chunks of 64
#define NC_H  24     // K=1536 -> 24 chunks of 64

// ---------------- scratch: chunk-major, pre-swizzled fp16 layouts ----------------
__device__ __align__(1024) __half g_act[(size_t)NC_A * NTOK * 64];
__device__ __align__(1024) __half g_hid[(size_t)NC_H * NTOK * 64];
__device__ __align__(256) __half g_qkv [(size_t)NTOK * 1152];     // fp16 row-major
__device__ __align__(256) float  g_xres[(size_t)NTOK * 384];
// weights: [NC chunks][N][64] single fp16
__device__ __align__(1024) __half g_wq[(size_t)NC_A * 1152 * 64];
__device__ __align__(1024) __half g_wp[(size_t)NC_A *  384 * 64];
__device__ __align__(1024) __half g_w1[(size_t)NC_A * 1536 * 64];
__device__ __align__(1024) __half g_w2[(size_t)NC_H *  384 * 64];

// ---------------- PTX helpers ----------------
__device__ __forceinline__ uint32_t smem_u32(const void* p) {
    uint32_t a;
    asm("{ .reg .u64 t; cvta.to.shared.u64 t, %1; cvt.u32.u64 %0, t; }" : "=r"(a) : "l"(p));
    return a;
}
#define MBARRIER_INIT(mb, c) \
    asm volatile("mbarrier.init.shared.b64 [%0], %1;" :: "r"((uint32_t)(mb)), "r"((uint32_t)(c)) : "memory")
#define MBARRIER_EXPECT_TX(mb, n) \
    asm volatile("mbarrier.arrive.expect_tx.shared.b64 _, [%0], %1;" :: "r"((uint32_t)(mb)), "r"((uint32_t)(n)) : "memory")
#define MBARRIER_WAIT_PARITY(mb, par) do { \
    uint32_t _m = (uint32_t)(mb), _p = (uint32_t)(par), _d; \
    asm volatile("{\n\t.reg .pred p;\n\t" \
        "mbarrier.try_wait.parity.acquire.cta.shared::cta.b64 p, [%1], %2;\n\t" \
        "selp.b32 %0, 1, 0, p;\n\t}" : "=r"(_d) : "r"(_m), "r"(_p) : "memory"); \
    if (!_d) { \
        asm volatile("{\n\t.reg .pred P1;\n\t" \
            "WL_%=:\n\t" \
            "mbarrier.try_wait.parity.acquire.cta.shared::cta.b64 P1, [%0], %1, 0x989680;\n\t" \
            "@P1 bra.uni WD_%=;\n\t" \
            "bra.uni WL_%=;\n\t" \
            "WD_%=:\n\t}" :: "r"(_m), "r"(_p) : "memory"); \
    } } while (0)
#define BULK_G2S(dst, src, n, mb) \
    asm volatile("cp.async.bulk.shared::cluster.global.mbarrier::complete_tx::bytes [%0], [%1], %2, [%3];" \
        :: "r"((uint32_t)(dst)), "l"(src), "r"((uint32_t)(n)), "r"((uint32_t)(mb)) : "memory")
#define FENCE_ASYNC() asm volatile("fence.proxy.async.shared::cta;" ::: "memory")
#define LDSM_X4(r0, r1, r2, r3, addr) \
    asm volatile("ldmatrix.sync.aligned.m8n8.x4.shared.b16 {%0,%1,%2,%3}, [%4];" \
                 : "=r"(r0), "=r"(r1), "=r"(r2), "=r"(r3) : "r"(addr))

__device__ __forceinline__ void mma16816(float* c, const uint32_t* a, const uint32_t* b) {
    asm volatile("mma.sync.aligned.m16n8k16.row.col.f32.f16.f16.f32 "
        "{%0,%1,%2,%3}, {%4,%5,%6,%7}, {%8,%9}, {%0,%1,%2,%3};"
        : "+f"(c[0]), "+f"(c[1]), "+f"(c[2]), "+f"(c[3])
        : "r"(a[0]), "r"(a[1]), "r"(a[2]), "r"(a[3]), "r"(b[0]), "r"(b[1]));
}

// window-order row -> sequence row (roll map; same both directions)
__device__ __forceinline__ int win_to_seq(int r) {
    int n  = r % WN;
    int t  = r / WN;
    int wc = t & 7, wr = (t >> 3) & 7, b = t >> 6;
    int n7 = n / 7;
    int h = wr * 7 + n7, w = wc * 7 + (n - n7 * 7);
    int dh = h + 3; if (dh >= HHs) dh -= HHs;
    int dw = w + 3; if (dw >= HHs) dw -= HHs;
    return (b * HHs + dh) * HHs + dw;
}

// fp16 store of 2 adjacent cols into chunk-major swizzled layout (k even)
__device__ __forceinline__ void h_store2(__half* base, int rows, int tok, int k,
                                         float v0, float v1) {
    int ch  = k >> 6;
    int idx = ((((k >> 3) & 7) ^ (tok & 7)) << 3) + (k & 7);
    *(__half2*)(base + ((size_t)ch * rows + tok) * 64 + idx) = __floats2half2_rn(v0, v1);
}

// ---------------- weight prep: W[K][N] fp32 -> [NC][N][64] swizzled fp16 ----------------
__global__ void wprep(const float* __restrict__ W, int K, int N, __half* __restrict__ O)
{
    __shared__ float t[32][33];
    int nb = blockIdx.x * 32, kb = blockIdx.y * 32;
    for (int i = threadIdx.y; i < 32; i += 8)
        t[i][threadIdx.x] = W[(size_t)(kb + i) * N + nb + threadIdx.x];
    __syncthreads();
    for (int i = threadIdx.y; i < 32; i += 8) {
        float v = t[threadIdx.x][i];
        int k = kb + threadIdx.x, n = nb + i;
        int ch  = k >> 6;
        int idx = ((((k >> 3) & 7) ^ (n & 7)) << 3) + (k & 7);
        O[((size_t)ch * N + n) * 64 + idx] = __float2half_rn(v);
    }
}

// ---------------- LayerNorm -> chunked fp16 (one warp per token) ----------------
template<bool PERM>
__global__ void ln_kernel(const float* __restrict__ X, const float* __restrict__ G,
                          const float* __restrict__ Bv, __half* __restrict__ Y)
{
    int gw   = (blockIdx.x * blockDim.x + threadIdx.x) >> 5;
    int lane = threadIdx.x & 31;
    if (gw >= NTOK) return;
    int src = PERM ? win_to_seq(gw) : gw;
    const float4* xr = (const float4*)(X + (size_t)src * 384);
    float4 a = xr[lane], b = xr[32 + lane], c = xr[64 + lane];
    float s = a.x+a.y+a.z+a.w + b.x+b.y+b.z+b.w + c.x+c.y+c.z+c.w;
    float q = a.x*a.x+a.y*a.y+a.z*a.z+a.w*a.w
            + b.x*b.x+b.y*b.y+b.z*b.z+b.w*b.w
            + c.x*c.x+c.y*c.y+c.z*c.z+c.w*c.w;
    #pragma unroll
    for (int o = 16; o; o >>= 1) {
        s += __shfl_xor_sync(0xffffffffu, s, o);
        q += __shfl_xor_sync(0xffffffffu, q, o);
    }
    float mu  = s * (1.0f / 384.0f);
    float var = q * (1.0f / 384.0f) - mu * mu;
    float rs  = rsqrtf(var + 1e-5f);
    const float4* gg = (const float4*)G;
    const float4* bb = (const float4*)Bv;
    #pragma unroll
    for (int seg = 0; seg < 3; seg++) {
        float4 v  = (seg == 0) ? a : (seg == 1) ? b : c;
        float4 g4 = gg[seg * 32 + lane];
        float4 b4 = bb[seg * 32 + lane];
        int k0 = seg * 128 + lane * 4;
        float w0 = (v.x - mu) * rs * g4.x + b4.x;
        float w1 = (v.y - mu) * rs * g4.y + b4.y;
        float w2 = (v.z - mu) * rs * g4.z + b4.z;
        float w3 = (v.w - mu) * rs * g4.w + b4.w;
        h_store2(Y, NTOK, gw, k0,     w0, w1);
        h_store2(Y, NTOK, gw, k0 + 2, w2, w3);
    }
}

// ---------------- attention: fp16 qkv in, 1 thread per row ----------------
__global__ __launch_bounds__(64)
void attn_kernel(const __half* __restrict__ qkv, __half* __restrict__ O)
{
    __shared__ float kk[WN][32], vv[WN][32];
    int win = blockIdx.x, head = blockIdx.y;
    int t = threadIdx.x;
    const __half* base = qkv + (size_t)win * WN * 1152 + head * 32;
    for (int u = t; u < WN * 16; u += 64) {
        int m = u >> 4, p = (u & 15) * 2;
        float2 fk = __half22float2(*(const __half2*)(base + (size_t)m * 1152 + 384 + p));
        float2 fv = __half22float2(*(const __half2*)(base + (size_t)m * 1152 + 768 + p));
        kk[m][p] = fk.x; kk[m][p+1] = fk.y;
        vv[m][p] = fv.x; vv[m][p+1] = fv.y;
    }
    __syncthreads();
    if (t >= WN) return;
    float q[32];
    const __half2* qr = (const __half2*)(base + (size_t)t * 1152);
    #pragma unroll
    for (int j = 0; j < 16; j++) {
        float2 f = __half22float2(qr[j]);
        q[2*j] = f.x; q[2*j+1] = f.y;
    }
    float s[WN];
    #pragma unroll
    for (int m = 0; m < WN; m++) {
        float a = 0.0f;
        #pragma unroll
        for (int j = 0; j < 32; j++) a += q[j] * kk[m][j];
        s[m] = a * 0.17677669529663687f;
    }
    float mx = -1e30f;
    #pragma unroll
    for (int m = 0; m < WN; m++) mx = fmaxf(mx, s[m]);
    float sum = 0.0f;
    #pragma unroll
    for (int m = 0; m < WN; m++) { s[m] = __expf(s[m] - mx); sum += s[m]; }
    float inv = 1.0f / sum;
    float o[32];
    #pragma unroll
    for (int j = 0; j < 32; j++) o[j] = 0.0f;
    #pragma unroll
    for (int m = 0; m < WN; m++) {
        float w = s[m] * inv;
        #pragma unroll
        for (int j = 0; j < 32; j++) o[j] += w * vv[m][j];
    }
    int tok = win * WN + t;
    int k0 = head * 32;
    #pragma unroll
    for (int j = 0; j < 32; j += 2)
        h_store2(O, NTOK, tok, k0 + j, o[j], o[j + 1]);
}

// ---------------- fp16 GEMM: 128x128 CTA, stage = A16K + B16K, 3 stages ----------------
#define STAGES 3
#define STG_BYTES 32768
#define MBAR_OFF  98304
#define SMEM_DYN  (98304 + 64)

// EPI 0: qkv fp16   1: gelu -> chunked fp16   2: scatter+resid fp32   3: resid fp32
template<int EPI>
__global__ __launch_bounds__(256)
void gemm_mma(const __half* __restrict__ A, const __half* __restrict__ B,
              const float* __restrict__ bias, float* __restrict__ Co,
              __half* __restrict__ O2, const float* __restrict__ resid,
              int NC, int Nn)
{
    extern __shared__ __align__(1024) char sm[];
    uint32_t sb = smem_u32(sm);
    int tid = threadIdx.x, lane = tid & 31, wid = tid >> 5;
    int wm = wid & 1, wn = wid >> 1;           // 2(M) x 4(N) warps, warp tile 64x32
    int m0 = blockIdx.y * 128, n0 = blockIdx.x * 128;

    if (tid == 0) {
        #pragma unroll
        for (int s = 0; s < STAGES; s++) MBARRIER_INIT(sb + MBAR_OFF + s * 8, 1);
        FENCE_ASYNC();
    }
    __syncthreads();

    auto issue = [&](int j) {
        const char* asrc = (const char*)A + ((size_t)j * NTOK + m0) * 128;
        const char* bsrc = (const char*)B + ((size_t)j * Nn   + n0) * 128;
        int s = j % STAGES;
        uint32_t dst = sb + s * STG_BYTES;
        uint32_t mb  = sb + MBAR_OFF + s * 8;
        MBARRIER_EXPECT_TX(mb, 32768);
        BULK_G2S(dst,         asrc, 16384, mb);
        BULK_G2S(dst + 16384, bsrc, 16384, mb);
    };
    if (tid == 0) { issue(0); issue(1); issue(2); }

    float acc[4][4][4];
    #pragma unroll
    for (int i = 0; i < 4; i++)
        #pragma unroll
        for (int j = 0; j < 4; j++)
            #pragma unroll
            for (int u = 0; u < 4; u++) acc[i][j][u] = 0.0f;

    for (int i = 0; i < NC; i++) {
        int s = i % STAGES;
        MBARRIER_WAIT_PARITY(sb + MBAR_OFF + s * 8, (i / STAGES) & 1);

        uint32_t As = sb + s * STG_BYTES;
        uint32_t Bs = As + 16384;
        #pragma unroll
        for (int kk = 0; kk < 4; kk++) {
            int ch = kk * 2 + (lane >> 4);
            uint32_t b[4][2];
            #pragma unroll
            for (int j2 = 0; j2 < 2; j2++) {
                int row = wn * 32 + j2 * 16 + (lane & 15);
                uint32_t r0, r1, r2, r3;
                LDSM_X4(r0, r1, r2, r3,
                        Bs + (uint32_t)row * 128 + (uint32_t)((ch ^ (row & 7)) << 4));
                b[2*j2][0] = r0; b[2*j2][1] = r2;
                b[2*j2+1][0] = r1; b[2*j2+1][1] = r3;
            }
            #pragma unroll
            for (int ii = 0; ii < 4; ii++) {
                int row = wm * 64 + ii * 16 + (lane & 15);
                uint32_t a[4];
                LDSM_X4(a[0], a[1], a[2], a[3],
                        As + (uint32_t)row * 128 + (uint32_t)((ch ^ (row & 7)) << 4));
                #pragma unroll
                for (int j = 0; j < 4; j++) mma16816(acc[ii][j], a, b[j]);
            }
        }
        __syncthreads();
        if (tid == 0 && i + STAGES < NC) issue(i + STAGES);
    }

    // stage C through smem (fp32, stride 132) for coalesced epilogue
    float* smf = (float*)sm;
    #pragma unroll
    for (int i = 0; i < 4; i++)
        #pragma unroll
        for (int j = 0; j < 4; j++) {
            int br = wm * 64 + i * 16 + (lane >> 2);
            int bc = wn * 32 + j * 8 + 2 * (lane & 3);
            *(float2*)&smf[br * 132 + bc]       = make_float2(acc[i][j][0], acc[i][j][1]);
            *(float2*)&smf[(br + 8) * 132 + bc] = make_float2(acc[i][j][2], acc[i][j][3]);
        }
    __syncthreads();

    int r    = tid >> 1;
    int cb0  = (tid & 1) * 64;
    int grow = m0 + r;
    const float* srow = &smf[r * 132 + cb0];
    if (EPI == 0) {
        __half* dst = O2 + (size_t)grow * Nn + n0 + cb0;
        #pragma unroll
        for (int c = 0; c < 64; c += 2) {
            float v0 = srow[c]   + bias[n0+cb0+c];
            float v1 = srow[c+1] + bias[n0+cb0+c+1];
            *(__half2*)(dst + c) = __floats2half2_rn(v0, v1);
        }
    } else if (EPI == 1) {
        int gc0 = n0 + cb0;                    // multiple of 64
        int ch  = gc0 >> 6;
        __half* hp = O2 + ((size_t)ch * NTOK + grow) * 64;
        #pragma unroll
        for (int c = 0; c < 64; c += 2) {
            float v0 = srow[c]   + bias[gc0 + c];
            float v1 = srow[c+1] + bias[gc0 + c + 1];
            v0 = 0.5f * v0 * (1.0f + erff(v0 * 0.70710678118654752f));
            v1 = 0.5f * v1 * (1.0f + erff(v1 * 0.70710678118654752f));
            int idx = ((((c >> 3) & 7) ^ (grow & 7)) << 3) + (c & 7);
            *(__half2*)(hp + idx) = __floats2half2_rn(v0, v1);
        }
    } else {
        size_t orow = (EPI == 2) ? (size_t)win_to_seq(grow) * Nn : (size_t)grow * Nn;
        float* dst = Co + orow + n0 + cb0;
        const float* rp = resid + orow + n0 + cb0;
        #pragma unroll
        for (int c = 0; c < 64; c += 4) {
            float4 rr = *(const float4*)(rp + c);
            float4 o;
            o.x = srow[c+0] + bias[n0+cb0+c+0] + rr.x;
            o.y = srow[c+1] + bias[n0+cb0+c+1] + rr.y;
            o.z = srow[c+2] + bias[n0+cb0+c+2] + rr.z;
            o.w = srow[c+3] + bias[n0+cb0+c+3] + rr.w;
            *(float4*)(dst + c) = o;
        }
    }
}

// ---------------- launcher ----------------
extern "C" void kernel_launch(void* const* d_in, const int* in_sizes, int n_in,
                              void* d_out, int out_size)
{
    const float* x      = (const float*)d_in[0];
    const float* ln1_g  = (const float*)d_in[1];
    const float* ln1_b  = (const float*)d_in[2];
    const float* w_qkv  = (const float*)d_in[3];
    const float* b_qkv  = (const float*)d_in[4];
    const float* w_proj = (const float*)d_in[5];
    const float* b_proj = (const float*)d_in[6];
    const float* ln2_g  = (const float*)d_in[7];
    const float* ln2_b  = (const float*)d_in[8];
    const float* w_fc1  = (const float*)d_in[9];
    const float* b_fc1  = (const float*)d_in[10];
    const float* w_fc2  = (const float*)d_in[11];
    const float* b_fc2  = (const float*)d_in[12];
    float* out = (float*)d_out;

    __half *act, *hid, *qkv, *wq, *wp, *w1, *w2;
    float *xres;
    cudaGetSymbolAddress((void**)&act,  g_act);
    cudaGetSymbolAddress((void**)&hid,  g_hid);
    cudaGetSymbolAddress((void**)&qkv,  g_qkv);
    cudaGetSymbolAddress((void**)&xres, g_xres);
    cudaGetSymbolAddress((void**)&wq,   g_wq);
    cudaGetSymbolAddress((void**)&wp,   g_wp);
    cudaGetSymbolAddress((void**)&w1,   g_w1);
    cudaGetSymbolAddress((void**)&w2,   g_w2);

    cudaFuncSetAttribute(gemm_mma<0>, cudaFuncAttributeMaxDynamicSharedMemorySize, SMEM_DYN);
    cudaFuncSetAttribute(gemm_mma<1>, cudaFuncAttributeMaxDynamicSharedMemorySize, SMEM_DYN);
    cudaFuncSetAttribute(gemm_mma<2>, cudaFuncAttributeMaxDynamicSharedMemorySize, SMEM_DYN);
    cudaFuncSetAttribute(gemm_mma<3>, cudaFuncAttributeMaxDynamicSharedMemorySize, SMEM_DYN);

    // weight prep (single fp16)
    wprep<<<dim3(1152/32,  384/32), dim3(32, 8)>>>(w_qkv,  384,  1152, wq);
    wprep<<<dim3( 384/32,  384/32), dim3(32, 8)>>>(w_proj, 384,   384, wp);
    wprep<<<dim3(1536/32,  384/32), dim3(32, 8)>>>(w_fc1,  384,  1536, w1);
    wprep<<<dim3( 384/32, 1536/32), dim3(32, 8)>>>(w_fc2,  1536,  384, w2);

    const int MT = NTOK / 128;   // 784

    // 1) LN1 + roll + window partition -> act
    ln_kernel<true><<<NTOK / 8, 256>>>(x, ln1_g, ln1_b, act);
    // 2) QKV -> fp16
    gemm_mma<0><<<dim3(1152/128, MT), 256, SMEM_DYN>>>(act, wq, b_qkv, nullptr, qkv, nullptr, NC_A, 1152);
    // 3) attention -> act
    attn_kernel<<<dim3(NTOK / WN, 12), 64>>>(qkv, act);
    // 4) proj + reverse/roll + residual
    gemm_mma<2><<<dim3( 384/128, MT), 256, SMEM_DYN>>>(act, wp, b_proj, xres, nullptr, x, NC_A, 384);
    // 5) LN2 -> act
    ln_kernel<false><<<NTOK / 8, 256>>>(xres, ln2_g, ln2_b, act);
    // 6) FC1 + GELU -> hid
    gemm_mma<1><<<dim3(1536/128, MT), 256, SMEM_DYN>>>(act, w1, b_fc1, nullptr, hid, nullptr, NC_A, 1536);
    // 7) FC2 + residual -> out
    gemm_mma<3><<<dim3( 384/128, MT), 256, SMEM_DYN>>>(hid, w2, b_fc2, out, nullptr, xres, NC_H, 384);
}